// round 1
// baseline (speedup 1.0000x reference)
#include <cuda_runtime.h>

// Problem constants
#define DVOL 160
#define HWS  25600            // 160*160
#define VOL  4096000          // 160^3
#define NTOT 8192000          // 2 * 160^3

// Scratch: 5 blurred channels (p, t, p*p, t*t, p*t), planar layout.
__device__ float g_ch[5][NTOT];
__device__ double g_l1_sum;
__device__ double g_ssim_sum;

// Gaussian weights (size 11, sigma 1.5, normalized) as literals so ptxas can
// use FFMA-imm (rt 1/SMSP instead of 2).
#define GW_INIT {0.00102838f, 0.00759876f, 0.03600078f, 0.10936070f, \
                 0.21300554f, 0.26601172f, 0.21300554f, 0.10936070f, \
                 0.03600078f, 0.00759876f, 0.00102838f}

__global__ void k_init() {
    g_l1_sum = 0.0;
    g_ssim_sum = 0.0;
}

// ---------------------------------------------------------------------------
// Kernel 1: per (n,d) slice, fused W-blur + H-blur of the 5 product channels,
// 32x32 output tiles. Also accumulates the L1 sum.
// ---------------------------------------------------------------------------
__global__ __launch_bounds__(256) void k_blur_wh(
    const float* __restrict__ pred, const float* __restrict__ tgt)
{
    __shared__ float rp[42][45];          // raw pred tile (pitch 45: conflict-free)
    __shared__ float rt[42][45];          // raw target tile
    __shared__ float stA[5][42][33];      // W-blurred channels (pitch 33)
    __shared__ float red[8];

    const float GW[11] = GW_INIT;

    const int bz = blockIdx.z;            // n*160 + d
    const int n  = bz / DVOL;
    const int d  = bz % DVOL;
    const int h0 = blockIdx.y * 32;
    const int w0 = blockIdx.x * 32;
    const int base = n * VOL + d * HWS;
    const int tid = threadIdx.x;

    // --- load raw 42x42 halo region (zero padded) -------------------------
    for (int i = tid; i < 42 * 42; i += 256) {
        const int r = i / 42, c = i % 42;
        const int gh = h0 - 5 + r;
        const int gw = w0 - 5 + c;
        float p = 0.f, t = 0.f;
        if ((unsigned)gh < 160u && (unsigned)gw < 160u) {
            const int idx = base + gh * DVOL + gw;
            p = pred[idx];
            t = tgt[idx];
        }
        rp[r][c] = p;
        rt[r][c] = t;
    }
    __syncthreads();

    // --- L1 partial over the 32x32 interior -------------------------------
    float l1 = 0.f;
    for (int i = tid; i < 1024; i += 256) {
        const int hh = i >> 5, ww = i & 31;
        l1 += fabsf(rp[5 + hh][5 + ww] - rt[5 + hh][5 + ww]);
    }

    // --- phase A: blur along W with register rings ------------------------
    // thread = (row r in 0..41, col-group g in 0..5), each group covers 6 cols
    if (tid < 252) {
        const int g = tid / 42;
        const int r = tid - 42 * g;
        const int c0 = g * 6;

        float qp[11], qt[11], qpp[11], qtt[11], qpt[11];
#pragma unroll
        for (int k = 0; k < 10; k++) {
            const float p = rp[r][c0 + k];
            const float t = rt[r][c0 + k];
            qp[k] = p; qt[k] = t;
            qpp[k] = p * p; qtt[k] = t * t; qpt[k] = p * t;
        }
#pragma unroll
        for (int s = 0; s < 6; s++) {
            const int c = c0 + s;
            if (c < 32) {
                const float p = rp[r][c + 10];
                const float t = rt[r][c + 10];
                const int sl = (s + 10) % 11;
                qp[sl] = p; qt[sl] = t;
                qpp[sl] = p * p; qtt[sl] = t * t; qpt[sl] = p * t;
                float a0 = 0.f, a1 = 0.f, a2 = 0.f, a3 = 0.f, a4 = 0.f;
#pragma unroll
                for (int j = 0; j < 11; j++) {
                    const int q = (s + j) % 11;
                    const float w = GW[j];
                    a0 += w * qp[q];
                    a1 += w * qt[q];
                    a2 += w * qpp[q];
                    a3 += w * qtt[q];
                    a4 += w * qpt[q];
                }
                stA[0][r][c] = a0;
                stA[1][r][c] = a1;
                stA[2][r][c] = a2;
                stA[3][r][c] = a3;
                stA[4][r][c] = a4;
            }
        }
    }

    // reduce L1 (warp shuffles, then smem) — overlaps with phase A compute
#pragma unroll
    for (int o = 16; o; o >>= 1) l1 += __shfl_down_sync(0xffffffffu, l1, o);
    if ((tid & 31) == 0) red[tid >> 5] = l1;

    __syncthreads();   // stA ready + red ready

    if (tid == 0) {
        float s = 0.f;
#pragma unroll
        for (int k = 0; k < 8; k++) s += red[k];
        atomicAdd(&g_l1_sum, (double)s);
    }

    // --- phase B: blur along H with register ring, write to global --------
    // thread = (channel ch in 0..4, col ww in 0..31)
    if (tid < 160) {
        const int ch = tid >> 5;
        const int ww = tid & 31;
        float rb[11];
#pragma unroll
        for (int k = 0; k < 10; k++) rb[k] = stA[ch][k][ww];
        const int obase = base + h0 * DVOL + w0 + ww;
        float* __restrict__ out = g_ch[ch];
#pragma unroll
        for (int hh = 0; hh < 32; hh++) {
            rb[(hh + 10) % 11] = stA[ch][hh + 10][ww];
            float a = 0.f;
#pragma unroll
            for (int j = 0; j < 11; j++) a += GW[j] * rb[(hh + j) % 11];
            out[obase + hh * DVOL] = a;
        }
    }
}

// ---------------------------------------------------------------------------
// Kernel 2: blur along D (register ring, unroll-by-11 so ring slots are
// compile-time), compute SSIM map, reduce.
// grid: (51200/256, 2)  — y splits D into 2 segments of 80 for parallelism.
// ---------------------------------------------------------------------------
__global__ __launch_bounds__(256) void k_blur_d_ssim()
{
    const float GW[11] = GW_INIT;
    const int col = blockIdx.x * 256 + threadIdx.x;   // 0..51199
    const int n  = col / HWS;
    const int hw = col - n * HWS;
    const int dstart = blockIdx.y * 80;
    const int base = n * VOL + hw;

    float rg[5][11];
#pragma unroll
    for (int c = 0; c < 5; c++)
#pragma unroll
        for (int k = 0; k < 11; k++) rg[c][k] = 0.f;

    // preload depths dstart-5 .. dstart+4 into slots 0..9
#pragma unroll
    for (int k = 0; k < 10; k++) {
        const int dep = dstart - 5 + k;
        if (dep >= 0) {
            const int idx = base + dep * HWS;
#pragma unroll
            for (int c = 0; c < 5; c++) rg[c][k] = g_ch[c][idx];
        }
    }

    float ssim_acc = 0.f;
    for (int s0 = 0; s0 < 88; s0 += 11) {
#pragma unroll
        for (int u = 0; u < 11; u++) {
            const int s = s0 + u;
            const int dep = dstart + s + 5;
            const int sl = (u + 10) % 11;
            if (dep < DVOL) {
                const int idx = base + dep * HWS;
#pragma unroll
                for (int c = 0; c < 5; c++) rg[c][sl] = g_ch[c][idx];
            } else {
#pragma unroll
                for (int c = 0; c < 5; c++) rg[c][sl] = 0.f;
            }
            if (s < 80) {
                float mu1 = 0.f, mu2 = 0.f, e11 = 0.f, e22 = 0.f, e12 = 0.f;
#pragma unroll
                for (int j = 0; j < 11; j++) {
                    const int q = (u + j) % 11;
                    const float w = GW[j];
                    mu1 += w * rg[0][q];
                    mu2 += w * rg[1][q];
                    e11 += w * rg[2][q];
                    e22 += w * rg[3][q];
                    e12 += w * rg[4][q];
                }
                const float mu1sq = mu1 * mu1;
                const float mu2sq = mu2 * mu2;
                const float mu12  = mu1 * mu2;
                const float s1  = e11 - mu1sq;
                const float s2  = e22 - mu2sq;
                const float s12 = e12 - mu12;
                const float C1 = 1e-4f, C2 = 9e-4f;
                const float num = (2.f * mu12 + C1) * (2.f * s12 + C2);
                const float den = (mu1sq + mu2sq + C1) * (s1 + s2 + C2) + 1e-12f;
                ssim_acc += num / den;
            }
        }
    }

    // block reduction
    __shared__ float red[8];
#pragma unroll
    for (int o = 16; o; o >>= 1)
        ssim_acc += __shfl_down_sync(0xffffffffu, ssim_acc, o);
    if ((threadIdx.x & 31) == 0) red[threadIdx.x >> 5] = ssim_acc;
    __syncthreads();
    if (threadIdx.x == 0) {
        float s = 0.f;
#pragma unroll
        for (int k = 0; k < 8; k++) s += red[k];
        atomicAdd(&g_ssim_sum, (double)s);
    }
}

__global__ void k_final(float* __restrict__ out) {
    const double inv = 1.0 / (double)NTOT;
    const double l1   = g_l1_sum * inv;
    const double ssim = g_ssim_sum * inv;
    out[0] = (float)(0.7 * l1 + 0.3 * (1.0 - ssim));
}

extern "C" void kernel_launch(void* const* d_in, const int* in_sizes, int n_in,
                              void* d_out, int out_size)
{
    const float* pred = (const float*)d_in[0];
    const float* tgt  = (const float*)d_in[1];
    float* out = (float*)d_out;

    k_init<<<1, 1>>>();

    dim3 g1(5, 5, 2 * DVOL);          // w-tiles, h-tiles, n*d
    k_blur_wh<<<g1, 256>>>(pred, tgt);

    dim3 g2((2 * HWS) / 256, 2);      // 200 x 2
    k_blur_d_ssim<<<g2, 256>>>();

    k_final<<<1, 1>>>(out);
}